// round 7
// baseline (speedup 1.0000x reference)
#include <cuda_runtime.h>
#include <cstdint>

#define H 512
#define DK 64
#define NCLASS 4
#define VOCAB 5000
#define LW 32
#define NLEAF 20000
#define NPAR 20000
#define NTOT 40000
#define DEG 4
#define NLAYER 5
#define LMAX 256
#define GMAX 2048
#define NB_RED 125
#define RED_CHUNK 160

__device__ float g_nodeh[(size_t)NTOT * H];
__device__ float g_xepar[(size_t)NPAR * H];
__device__ float g_EbuT[(size_t)VOCAB * H];
__device__ float g_gz0[(size_t)NPAR * H];
__device__ float g_gr0[(size_t)NPAR * H];
__device__ float g_gh0[(size_t)NPAR * H];
__device__ float g_memv[(size_t)NPAR * H];
__device__ float g_mrv[(size_t)NPAR * H];
__device__ float g_zv[(size_t)NPAR * H];
__device__ int g_lvl[NPAR];
__device__ int g_hist[LMAX], g_lstart[LMAX], g_lofs[LMAX], g_order[NPAR];
__device__ int g_gbase[LMAX];
__device__ int g_grow[GMAX], g_gsz[GMAX];
__device__ int g_pgroup[NPAR];
__device__ int g_acnt[GMAX], g_bcnt[GMAX], g_ccnt[GMAX];
__device__ int g_ngrp, g_nlev, g_barcnt;
__device__ int g_qA, g_qB, g_qC;
__device__ volatile int g_barsense;
__device__ float g_pmax[NB_RED * H];

__device__ __forceinline__ float sigf(float x) { return 1.f / (1.f + __expf(-x)); }

// ---------------- launch 1: transpose + init ----------------
__global__ void k_setup(const float* __restrict__ E) {
    __shared__ float t[32][33];
    int x = blockIdx.x * 32 + threadIdx.x;
    int y0 = blockIdx.y * 32;
#pragma unroll
    for (int j = 0; j < 32; j += 8) {
        int y = y0 + threadIdx.y + j;
        t[threadIdx.y + j][threadIdx.x] = (x < VOCAB) ? E[(size_t)y * VOCAB + x] : 0.f;
    }
    __syncthreads();
    int xo = blockIdx.y * 32 + threadIdx.x;
    int yo0 = blockIdx.x * 32;
#pragma unroll
    for (int j = 0; j < 32; j += 8) {
        int yo = yo0 + threadIdx.y + j;
        if (yo < VOCAB) g_EbuT[(size_t)yo * H + xo] = t[threadIdx.x][threadIdx.y + j];
    }
    if (blockIdx.x == 0 && blockIdx.y == 0) {
        int tid = threadIdx.y * 32 + threadIdx.x;
        for (int i = tid; i < NPAR; i += 256) g_lvl[i] = -1;
        for (int i = tid; i < GMAX; i += 256) { g_acnt[i] = 0; g_bcnt[i] = 0; g_ccnt[i] = 0; }
        if (tid < LMAX) g_hist[tid] = 0;
        if (tid == 0) { g_barcnt = 0; g_barsense = 0; g_qA = 0; g_qB = 0; g_qC = 0; }
    }
}

// ---------------- launch 2: embed ----------------
__global__ void k_embed(const float* __restrict__ xw, const int* __restrict__ xi) {
    int n = blockIdx.x;
    int tid = threadIdx.x;   // 128
    __shared__ float s_w[LW];
    __shared__ int   s_i[LW];
    if (tid < LW) { s_w[tid] = xw[n * LW + tid]; s_i[tid] = xi[n * LW + tid]; }
    __syncthreads();
    float4 acc = make_float4(0.f, 0.f, 0.f, 0.f);
#pragma unroll 8
    for (int l = 0; l < LW; l++) {
        float4 e = ((const float4*)(g_EbuT + (size_t)s_i[l] * H))[tid];
        float w = s_w[l];
        acc.x += w * e.x; acc.y += w * e.y; acc.z += w * e.z; acc.w += w * e.w;
    }
    float4* dst = (n < NLEAF) ? (float4*)(g_nodeh + (size_t)n * H)
                              : (float4*)(g_xepar + (size_t)(n - NLEAF) * H);
    dst[tid] = acc;
}

// ---------------- launch 3: pre-GEMM (parent-id indexed) ----------------
__global__ void __launch_bounds__(256) k_pregemm(
    const float* __restrict__ Wz, const float* __restrict__ bz,
    const float* __restrict__ Wr, const float* __restrict__ br,
    const float* __restrict__ Wh, const float* __restrict__ bh)
{
    __shared__ float sX[32 * 132];
    __shared__ float sW[32 * 132];
    int sel = blockIdx.z;
    const float* W    = sel == 0 ? Wz : sel == 1 ? Wr : Wh;
    const float* bias = sel == 0 ? bz : sel == 1 ? br : bh;
    float* out        = sel == 0 ? g_gz0 : sel == 1 ? g_gr0 : g_gh0;
    int m0 = blockIdx.x * 128, n0 = blockIdx.y * 128;
    int t = threadIdx.x;
    int lrow = t >> 1, lk = (t & 1) * 16;
    int ty = t >> 4, tx = t & 15;
    float acc[8][8];
#pragma unroll
    for (int i = 0; i < 8; i++)
#pragma unroll
        for (int j = 0; j < 8; j++) acc[i][j] = 0.f;
    int xm = min(m0 + lrow, NPAR - 1);
    for (int kc = 0; kc < H; kc += 32) {
        const float* xr = g_xepar + (size_t)xm * H + kc + lk;
        const float* wr = W + (size_t)(n0 + lrow) * H + kc + lk;
#pragma unroll
        for (int q = 0; q < 4; q++) {
            float4 xv = *(const float4*)(xr + q * 4);
            float4 wv = *(const float4*)(wr + q * 4);
            sX[(lk + q * 4 + 0) * 132 + lrow] = xv.x;
            sX[(lk + q * 4 + 1) * 132 + lrow] = xv.y;
            sX[(lk + q * 4 + 2) * 132 + lrow] = xv.z;
            sX[(lk + q * 4 + 3) * 132 + lrow] = xv.w;
            sW[(lk + q * 4 + 0) * 132 + lrow] = wv.x;
            sW[(lk + q * 4 + 1) * 132 + lrow] = wv.y;
            sW[(lk + q * 4 + 2) * 132 + lrow] = wv.z;
            sW[(lk + q * 4 + 3) * 132 + lrow] = wv.w;
        }
        __syncthreads();
#pragma unroll
        for (int kk = 0; kk < 32; kk++) {
            float4 a0 = *(const float4*)(sX + kk * 132 + ty * 8);
            float4 a1 = *(const float4*)(sX + kk * 132 + ty * 8 + 4);
            float4 b0 = *(const float4*)(sW + kk * 132 + tx * 8);
            float4 b1 = *(const float4*)(sW + kk * 132 + tx * 8 + 4);
            float a[8] = {a0.x,a0.y,a0.z,a0.w,a1.x,a1.y,a1.z,a1.w};
            float b[8] = {b0.x,b0.y,b0.z,b0.w,b1.x,b1.y,b1.z,b1.w};
#pragma unroll
            for (int i = 0; i < 8; i++)
#pragma unroll
                for (int j = 0; j < 8; j++) acc[i][j] += a[i] * b[j];
        }
        __syncthreads();
    }
#pragma unroll
    for (int i = 0; i < 8; i++) {
        int m = m0 + ty * 8 + i;
        if (m >= NPAR) continue;
        float* dst = out + (size_t)m * H + n0 + tx * 8;
#pragma unroll
        for (int j = 0; j < 8; j++) dst[j] = acc[i][j] + bias[n0 + tx * 8 + j];
    }
}

// ---------------- launch 4: persistent dataflow pipeline ----------------
__device__ __forceinline__ void gridbar(int nb, int& sense) {
    __syncthreads();
    if (threadIdx.x == 0) {
        sense ^= 1;
        __threadfence();
        if (atomicAdd(&g_barcnt, 1) == nb - 1) {
            atomicExch(&g_barcnt, 0);
            __threadfence();
            g_barsense = sense;
        } else {
            while (g_barsense != sense) __nanosleep(32);
        }
        __threadfence();
    }
    __syncthreads();
}

#define AH(buf,k,head) (((buf)*4+(k))*8+(head))*65

__device__ int attn_core(int p, const int* __restrict__ tree, float* SBUF,
                         int* s_child, float* s_sc, float* s_p) {
    int tid = threadIdx.x;
    __syncthreads();
    if (tid < DEG) s_child[tid] = tree[p * DEG + tid];
    __syncthreads();
#pragma unroll
    for (int j = 0; j < 8; j++) {
        int idx = tid + j * 256;
        int k = idx >> 9, col = idx & 511, head = col >> 6, d = col & 63;
        int c = s_child[k];
        SBUF[AH(0, k, head) + d] = (c > -1) ? __ldcg(&g_nodeh[(size_t)c * H + col]) : 0.f;
    }
    __syncthreads();
    int cur = 0;
    for (int layer = 0; layer < NLAYER; layer++) {
        if (tid < 128) {
            int head = tid >> 4, q = (tid >> 2) & 3, kk = tid & 3;
            const float* hq = &SBUF[AH(cur, q, head)];
            const float* hk = &SBUF[AH(cur, kk, head)];
            float s = 0.f;
#pragma unroll
            for (int d = 0; d < DK; d++) s += hq[d] * hk[d];
            s *= 0.125f;
            if (s_child[kk] <= -1) s = -1e9f;
            s_sc[(head * 4 + q) * 4 + kk] = s;
        }
        __syncthreads();
        if (tid < 32) {
            int head = tid >> 2, q = tid & 3;
            const float* r = &s_sc[(head * 4 + q) * 4];
            float m = fmaxf(fmaxf(r[0], r[1]), fmaxf(r[2], r[3]));
            float e0 = __expf(r[0] - m), e1 = __expf(r[1] - m);
            float e2 = __expf(r[2] - m), e3 = __expf(r[3] - m);
            float inv = 1.f / (e0 + e1 + e2 + e3);
            float* pr = &s_p[(head * 4 + q) * 4];
            pr[0] = e0 * inv; pr[1] = e1 * inv; pr[2] = e2 * inv; pr[3] = e3 * inv;
        }
        __syncthreads();
        int nxt = cur ^ 1;
#pragma unroll
        for (int j = 0; j < 2; j++) {
            int col = tid + j * 256, head = col >> 6, d = col & 63;
            float v0 = SBUF[AH(cur, 0, head) + d];
            float v1 = SBUF[AH(cur, 1, head) + d];
            float v2 = SBUF[AH(cur, 2, head) + d];
            float v3 = SBUF[AH(cur, 3, head) + d];
#pragma unroll
            for (int q = 0; q < 4; q++) {
                const float* pr = &s_p[(head * 4 + q) * 4];
                SBUF[AH(nxt, q, head) + d] = pr[0] * v0 + pr[1] * v1 + pr[2] * v2 + pr[3] * v3;
            }
        }
        __syncthreads();
        cur = nxt;
    }
    return cur;
}

// B tile: rows [grow, grow+gsz), dims [n0, n0+64), Uz & Ur
__device__ void phaseB_df(int grow, int gsz, int n0,
                          const float* __restrict__ Uz, const float* __restrict__ Ur,
                          float* SBUF, int* s_pid) {
    float* sA  = SBUF;
    float* sWz = SBUF + 1056;
    float* sWr = SBUF + 1056 + 32 * 65;
    int tid = threadIdx.x;
    int ty = tid >> 4, tx = tid & 15;
    int am = tid >> 3, ak = (tid & 7) * 4;
    int wn = tid >> 2, wk = (tid & 3) * 8;
    float az[2][4], ar[2][4];
#pragma unroll
    for (int i = 0; i < 2; i++)
#pragma unroll
        for (int j = 0; j < 4; j++) { az[i][j] = 0.f; ar[i][j] = 0.f; }
    __syncthreads();
    if (tid < 32) s_pid[tid] = g_order[grow + min(tid, gsz - 1)];
    int rrow = grow + ((am < gsz) ? am : 0);
    for (int kc = 0; kc < H; kc += 32) {
        float4 a = __ldcg((const float4*)&g_memv[(size_t)rrow * H + kc + ak]);
        sA[(ak + 0) * 33 + am] = a.x; sA[(ak + 1) * 33 + am] = a.y;
        sA[(ak + 2) * 33 + am] = a.z; sA[(ak + 3) * 33 + am] = a.w;
        const float* wz = Uz + (size_t)(n0 + wn) * H + kc + wk;
        const float* wr = Ur + (size_t)(n0 + wn) * H + kc + wk;
#pragma unroll
        for (int q = 0; q < 2; q++) {
            float4 zv = *(const float4*)(wz + q * 4);
            float4 rv = *(const float4*)(wr + q * 4);
            sWz[(wk + q * 4 + 0) * 65 + wn] = zv.x;
            sWz[(wk + q * 4 + 1) * 65 + wn] = zv.y;
            sWz[(wk + q * 4 + 2) * 65 + wn] = zv.z;
            sWz[(wk + q * 4 + 3) * 65 + wn] = zv.w;
            sWr[(wk + q * 4 + 0) * 65 + wn] = rv.x;
            sWr[(wk + q * 4 + 1) * 65 + wn] = rv.y;
            sWr[(wk + q * 4 + 2) * 65 + wn] = rv.z;
            sWr[(wk + q * 4 + 3) * 65 + wn] = rv.w;
        }
        __syncthreads();
#pragma unroll
        for (int kk = 0; kk < 32; kk++) {
            float a0 = sA[kk * 33 + ty * 2], a1 = sA[kk * 33 + ty * 2 + 1];
#pragma unroll
            for (int n = 0; n < 4; n++) {
                float bz = sWz[kk * 65 + tx * 4 + n];
                float br = sWr[kk * 65 + tx * 4 + n];
                az[0][n] += a0 * bz; az[1][n] += a1 * bz;
                ar[0][n] += a0 * br; ar[1][n] += a1 * br;
            }
        }
        __syncthreads();
    }
#pragma unroll
    for (int mi = 0; mi < 2; mi++) {
        int m = ty * 2 + mi;
        if (m >= gsz) continue;
        int p = s_pid[m];
        size_t rb = (size_t)(grow + m) * H + n0 + tx * 4;
        size_t pb = (size_t)p * H + n0 + tx * 4;
#pragma unroll
        for (int n = 0; n < 4; n++) {
            float z = sigf(__ldcg(&g_gz0[pb + n]) + az[mi][n]);
            float r = sigf(__ldcg(&g_gr0[pb + n]) + ar[mi][n]);
            float mem = __ldcg(&g_memv[rb + n]);
            __stcg(&g_zv[rb + n], z);
            __stcg(&g_mrv[rb + n], mem * r);
        }
    }
}

__device__ void phaseC_df(int grow, int gsz, int n0,
                          const float* __restrict__ Uh, float* SBUF, int* s_pid) {
    float* sA = SBUF;
    float* sW = SBUF + 1056;
    int tid = threadIdx.x;
    int ty = tid >> 4, tx = tid & 15;
    int am = tid >> 3, ak = (tid & 7) * 4;
    int wn = tid >> 2, wk = (tid & 3) * 8;
    float ah[2][4];
#pragma unroll
    for (int i = 0; i < 2; i++)
#pragma unroll
        for (int j = 0; j < 4; j++) ah[i][j] = 0.f;
    __syncthreads();
    if (tid < 32) s_pid[tid] = g_order[grow + min(tid, gsz - 1)];
    int rrow = grow + ((am < gsz) ? am : 0);
    for (int kc = 0; kc < H; kc += 32) {
        float4 a = __ldcg((const float4*)&g_mrv[(size_t)rrow * H + kc + ak]);
        sA[(ak + 0) * 33 + am] = a.x; sA[(ak + 1) * 33 + am] = a.y;
        sA[(ak + 2) * 33 + am] = a.z; sA[(ak + 3) * 33 + am] = a.w;
        const float* wh = Uh + (size_t)(n0 + wn) * H + kc + wk;
#pragma unroll
        for (int q = 0; q < 2; q++) {
            float4 hv = *(const float4*)(wh + q * 4);
            sW[(wk + q * 4 + 0) * 65 + wn] = hv.x;
            sW[(wk + q * 4 + 1) * 65 + wn] = hv.y;
            sW[(wk + q * 4 + 2) * 65 + wn] = hv.z;
            sW[(wk + q * 4 + 3) * 65 + wn] = hv.w;
        }
        __syncthreads();
#pragma unroll
        for (int kk = 0; kk < 32; kk++) {
            float a0 = sA[kk * 33 + ty * 2], a1 = sA[kk * 33 + ty * 2 + 1];
#pragma unroll
            for (int n = 0; n < 4; n++) {
                float b = sW[kk * 65 + tx * 4 + n];
                ah[0][n] += a0 * b; ah[1][n] += a1 * b;
            }
        }
        __syncthreads();
    }
#pragma unroll
    for (int mi = 0; mi < 2; mi++) {
        int m = ty * 2 + mi;
        if (m >= gsz) continue;
        int p = s_pid[m];
        size_t rb = (size_t)(grow + m) * H + n0 + tx * 4;
        size_t pb = (size_t)p * H + n0 + tx * 4;
#pragma unroll
        for (int n = 0; n < 4; n++) {
            float c = tanhf(__ldcg(&g_gh0[pb + n]) + ah[mi][n]);
            float z = __ldcg(&g_zv[rb + n]);
            float mem = __ldcg(&g_memv[rb + n]);
            __stcg(&g_nodeh[(size_t)(NLEAF + p) * H + n0 + tx * 4 + n],
                   z * mem + (1.f - z) * c);
        }
    }
}

__global__ void __launch_bounds__(256) k_main(
    const int* __restrict__ tree,
    const float* __restrict__ Uz, const float* __restrict__ Ur,
    const float* __restrict__ Uh)
{
    __shared__ float SBUF[5696];
    __shared__ float s_sc[128], s_p[128];
    __shared__ int s_child[DEG], s_pid[32];
    __shared__ int s_task;
    int nb = gridDim.x;
    int sense = 0;
    int tid = threadIdx.x;
    int gstride = nb * 256;

    // ---- topo prologue ----
    for (int p = blockIdx.x * 256 + tid; p < NPAR; p += gstride) {
        int lv = 0;
#pragma unroll
        for (int k = 0; k < DEG; k++) {
            int c = tree[p * DEG + k];
            if (c >= NLEAF) {
                int v;
                while ((v = atomicAdd(&g_lvl[c - NLEAF], 0)) < 0) __nanosleep(40);
                lv = max(lv, v + 1);
            }
        }
        if (lv > LMAX - 1) lv = LMAX - 1;
        atomicExch(&g_lvl[p], lv);
    }
    gridbar(nb, sense);
    for (int p = blockIdx.x * 256 + tid; p < NPAR; p += gstride)
        atomicAdd(&g_hist[g_lvl[p]], 1);
    gridbar(nb, sense);
    if (blockIdx.x == 0 && tid == 0) {
        int acc = 0, nl = 1;
        for (int i = 0; i < LMAX; i++) {
            g_lstart[i] = acc; g_lofs[i] = acc;
            acc += g_hist[i];
            if (g_hist[i] > 0) nl = i + 1;
        }
        g_nlev = nl;
        int G = 0;
        for (int l = 0; l < nl; l++) {
            int c = g_hist[l];
            g_gbase[l] = G;
            for (int k = 0; k * 32 < c; k++) {
                g_grow[G] = g_lstart[l] + k * 32;
                g_gsz[G] = min(32, c - k * 32);
                G++;
            }
        }
        g_ngrp = G;
    }
    gridbar(nb, sense);
    for (int p = blockIdx.x * 256 + tid; p < NPAR; p += gstride) {
        int lvl = g_lvl[p];
        int row = atomicAdd(&g_lofs[lvl], 1);
        g_order[row] = p;
        g_pgroup[p] = g_gbase[lvl] + (row - g_lstart[lvl]) / 32;
    }
    gridbar(nb, sense);

    int G = g_ngrp;
    int NA = nb * 45 / 100; if (NA < 1) NA = 1;
    int NB = nb * 35 / 100; if (NB < 1) NB = 1;

    if (blockIdx.x < NA) {
        // ---------- attention stage ----------
        while (true) {
            if (tid == 0) s_task = atomicAdd(&g_qA, 1);
            __syncthreads();
            int row = s_task;
            if (row >= NPAR) break;
            int p = g_order[row];
            if (tid < DEG) {
                int c = tree[p * DEG + tid];
                if (c >= NLEAF) {
                    int g = g_pgroup[c - NLEAF];
                    while (atomicAdd(&g_ccnt[g], 0) < 8) __nanosleep(80);
                    __threadfence();
                }
            }
            __syncthreads();
            int cur = attn_core(p, tree, SBUF, s_child, s_sc, s_p);
            int cc = (s_child[0] > -1) + (s_child[1] > -1) + (s_child[2] > -1) + (s_child[3] > -1);
            float denom = (float)max(cc, 1);
#pragma unroll
            for (int j = 0; j < 2; j++) {
                int col = tid + j * 256, head = col >> 6, d = col & 63;
                float m = 0.f;
#pragma unroll
                for (int k = 0; k < DEG; k++)
                    if (s_child[k] > -1) m += SBUF[AH(cur, k, head) + d];
                __stcg(&g_memv[(size_t)row * H + col], m / denom);
            }
            __syncthreads();
            if (tid == 0) {
                __threadfence();
                atomicAdd(&g_acnt[g_pgroup[p]], 1);
            }
        }
    } else if (blockIdx.x < NA + NB) {
        // ---------- B stage: z,r gates ----------
        while (true) {
            if (tid == 0) s_task = atomicAdd(&g_qB, 1);
            __syncthreads();
            int t = s_task;
            if (t >= 8 * G) break;
            int g = t >> 3, j = t & 7;
            int grow = g_grow[g], gsz = g_gsz[g];
            if (tid == 0) {
                while (atomicAdd(&g_acnt[g], 0) < gsz) __nanosleep(80);
                __threadfence();
            }
            __syncthreads();
            phaseB_df(grow, gsz, j * 64, Uz, Ur, SBUF, s_pid);
            __syncthreads();
            if (tid == 0) {
                __threadfence();
                atomicAdd(&g_bcnt[g], 1);
            }
        }
    } else {
        // ---------- C stage: candidate + h ----------
        while (true) {
            if (tid == 0) s_task = atomicAdd(&g_qC, 1);
            __syncthreads();
            int t = s_task;
            if (t >= 8 * G) break;
            int g = t >> 3, j = t & 7;
            int grow = g_grow[g], gsz = g_gsz[g];
            if (tid == 0) {
                while (atomicAdd(&g_bcnt[g], 0) < 8) __nanosleep(80);
                __threadfence();
            }
            __syncthreads();
            phaseC_df(grow, gsz, j * 64, Uh, SBUF, s_pid);
            __syncthreads();
            if (tid == 0) {
                __threadfence();
                atomicAdd(&g_ccnt[g], 1);
            }
        }
    }
}

// ---------------- reductions ----------------
__global__ void k_redmax() {
    int tid = threadIdx.x;
    int b = blockIdx.x;
    const float* base = g_nodeh + (size_t)NLEAF * H;
    float m = -3.4e38f;
    for (int p = b * RED_CHUNK; p < (b + 1) * RED_CHUNK; p++)
        m = fmaxf(m, base[(size_t)p * H + tid]);
    g_pmax[b * H + tid] = m;
}

__global__ void k_final(const float* __restrict__ Wo, const float* __restrict__ bo,
                        float* __restrict__ out) {
    __shared__ float s_f[H];
    __shared__ float s_logit[NCLASS];
    int tid = threadIdx.x;   // 512
    float m = g_pmax[tid];
    for (int b = 1; b < NB_RED; b++) m = fmaxf(m, g_pmax[b * H + tid]);
    s_f[tid] = m;
    __syncthreads();
    int w = tid >> 5, lane = tid & 31;
    if (w < NCLASS) {
        float acc = 0.f;
        for (int j = lane; j < H; j += 32) acc += Wo[w * H + j] * s_f[j];
#pragma unroll
        for (int o = 16; o; o >>= 1) acc += __shfl_down_sync(0xffffffffu, acc, o);
        if (lane == 0) s_logit[w] = acc + bo[w];
    }
    __syncthreads();
    if (tid == 0) {
        float mx = s_logit[0];
        for (int i = 1; i < NCLASS; i++) mx = fmaxf(mx, s_logit[i]);
        float e[NCLASS], s = 0.f;
        for (int i = 0; i < NCLASS; i++) { e[i] = __expf(s_logit[i] - mx); s += e[i]; }
        for (int i = 0; i < NCLASS; i++) out[i] = e[i] / s;
    }
}

extern "C" void kernel_launch(void* const* d_in, const int* in_sizes, int n_in,
                              void* d_out, int out_size) {
    const float* x_word  = (const float*)d_in[0];
    const int*   x_index = (const int*)  d_in[1];
    const int*   tree    = (const int*)  d_in[2];
    const float* E_bu    = (const float*)d_in[3];
    const float* W_z = (const float*)d_in[4];
    const float* U_z = (const float*)d_in[5];
    const float* b_z = (const float*)d_in[6];
    const float* W_r = (const float*)d_in[7];
    const float* U_r = (const float*)d_in[8];
    const float* b_r = (const float*)d_in[9];
    const float* W_h = (const float*)d_in[10];
    const float* U_h = (const float*)d_in[11];
    const float* b_h = (const float*)d_in[12];
    const float* W_out = (const float*)d_in[13];
    const float* b_out = (const float*)d_in[14];
    float* out = (float*)d_out;

    static int nb_main = 0;
    if (nb_main == 0) {
        int dev = 0; cudaGetDevice(&dev);
        int nsm = 0; cudaDeviceGetAttribute(&nsm, cudaDevAttrMultiProcessorCount, dev);
        int perSM = 0;
        cudaOccupancyMaxActiveBlocksPerMultiprocessor(&perSM, k_main, 256, 0);
        if (perSM < 1) perSM = 1;
        nb_main = nsm * perSM;
    }

    dim3 tb(32, 8), tg((VOCAB + 31) / 32, H / 32);
    k_setup<<<tg, tb>>>(E_bu);
    k_embed<<<NTOT, 128>>>(x_word, x_index);
    k_pregemm<<<dim3((NPAR + 127) / 128, H / 128, 3), 256>>>(W_z, b_z, W_r, b_r, W_h, b_h);
    k_main<<<nb_main, 256>>>(tree, U_z, U_r, U_h);
    k_redmax<<<NB_RED, H>>>();
    k_final<<<1, H>>>(W_out, b_out, out);
}

// round 8
// speedup vs baseline: 1.0473x; 1.0473x over previous
#include <cuda_runtime.h>
#include <cstdint>

#define H 512
#define DK 64
#define NCLASS 4
#define VOCAB 5000
#define LW 32
#define NLEAF 20000
#define NPAR 20000
#define NTOT 40000
#define DEG 4
#define NLAYER 5
#define LMAX 256
#define NB_RED 125
#define RED_CHUNK 160

typedef unsigned long long u64;

__device__ float g_nodeh[(size_t)NTOT * H];
__device__ float g_xepar[(size_t)NPAR * H];
__device__ float g_EbuT[(size_t)VOCAB * H];
__device__ float g_gz0[(size_t)NPAR * H];
__device__ float g_gr0[(size_t)NPAR * H];
__device__ float g_gh0[(size_t)NPAR * H];
__device__ float g_memv[(size_t)NPAR * H];
__device__ float g_mrv[(size_t)NPAR * H];
__device__ float g_zv[(size_t)NPAR * H];
__device__ int g_lvl[NPAR];
__device__ int g_hist[LMAX], g_lstart[LMAX], g_lofs[LMAX], g_order[NPAR];
__device__ int g_nlev, g_barcnt;
__device__ volatile int g_barsense;
__device__ float g_pmax[NB_RED * H];

__device__ __forceinline__ float sigf(float x) { return 1.f / (1.f + __expf(-x)); }

// ---- packed f32x2 helpers (FFMA2 via PTX; ptxas never auto-fuses) ----
__device__ __forceinline__ u64 pk2(float x, float y) {
    u64 r; asm("mov.b64 %0, {%1, %2};" : "=l"(r) : "f"(x), "f"(y)); return r;
}
__device__ __forceinline__ void fma2(u64& d, u64 a, u64 b) {
    asm("fma.rn.f32x2 %0, %1, %2, %0;" : "+l"(d) : "l"(a), "l"(b));
}
__device__ __forceinline__ float2 upk2(u64 v) {
    float2 r; asm("mov.b64 {%0, %1}, %2;" : "=f"(r.x), "=f"(r.y) : "l"(v)); return r;
}

// ---------------- launch 1: transpose + init ----------------
__global__ void k_setup(const float* __restrict__ E) {
    __shared__ float t[32][33];
    int x = blockIdx.x * 32 + threadIdx.x;
    int y0 = blockIdx.y * 32;
#pragma unroll
    for (int j = 0; j < 32; j += 8) {
        int y = y0 + threadIdx.y + j;
        t[threadIdx.y + j][threadIdx.x] = (x < VOCAB) ? E[(size_t)y * VOCAB + x] : 0.f;
    }
    __syncthreads();
    int xo = blockIdx.y * 32 + threadIdx.x;
    int yo0 = blockIdx.x * 32;
#pragma unroll
    for (int j = 0; j < 32; j += 8) {
        int yo = yo0 + threadIdx.y + j;
        if (yo < VOCAB) g_EbuT[(size_t)yo * H + xo] = t[threadIdx.x][threadIdx.y + j];
    }
    if (blockIdx.x == 0 && blockIdx.y == 0) {
        int tid = threadIdx.y * 32 + threadIdx.x;
        for (int i = tid; i < NPAR; i += 256) g_lvl[i] = -1;
        if (tid < LMAX) g_hist[tid] = 0;
        if (tid == 0) { g_barcnt = 0; g_barsense = 0; }
    }
}

// ---------------- launch 2: embed ----------------
__global__ void k_embed(const float* __restrict__ xw, const int* __restrict__ xi) {
    int n = blockIdx.x;
    int tid = threadIdx.x;   // 128
    __shared__ float s_w[LW];
    __shared__ int   s_i[LW];
    if (tid < LW) { s_w[tid] = xw[n * LW + tid]; s_i[tid] = xi[n * LW + tid]; }
    __syncthreads();
    float4 acc = make_float4(0.f, 0.f, 0.f, 0.f);
#pragma unroll 8
    for (int l = 0; l < LW; l++) {
        float4 e = ((const float4*)(g_EbuT + (size_t)s_i[l] * H))[tid];
        float w = s_w[l];
        acc.x += w * e.x; acc.y += w * e.y; acc.z += w * e.z; acc.w += w * e.w;
    }
    float4* dst = (n < NLEAF) ? (float4*)(g_nodeh + (size_t)n * H)
                              : (float4*)(g_xepar + (size_t)(n - NLEAF) * H);
    dst[tid] = acc;
}

// ---------------- launch 3: pre-GEMM, f32x2 core ----------------
// BM=128, BN=128, BK=32, 256 thr, 8x8 per thread
__global__ void __launch_bounds__(256) k_pregemm(
    const float* __restrict__ Wz, const float* __restrict__ bz,
    const float* __restrict__ Wr, const float* __restrict__ br,
    const float* __restrict__ Wh, const float* __restrict__ bh)
{
    __shared__ float sX[32 * 132];
    __shared__ float sW[32 * 132];
    int sel = blockIdx.z;
    const float* W    = sel == 0 ? Wz : sel == 1 ? Wr : Wh;
    const float* bias = sel == 0 ? bz : sel == 1 ? br : bh;
    float* out        = sel == 0 ? g_gz0 : sel == 1 ? g_gr0 : g_gh0;
    int m0 = blockIdx.x * 128, n0 = blockIdx.y * 128;
    int t = threadIdx.x;
    int lrow = t >> 1, lk = (t & 1) * 16;
    int ty = t >> 4, tx = t & 15;
    u64 acc[8][4];
#pragma unroll
    for (int i = 0; i < 8; i++)
#pragma unroll
        for (int j = 0; j < 4; j++) acc[i][j] = 0ULL;
    int xm = min(m0 + lrow, NPAR - 1);
    for (int kc = 0; kc < H; kc += 32) {
        const float* xr = g_xepar + (size_t)xm * H + kc + lk;
        const float* wr = W + (size_t)(n0 + lrow) * H + kc + lk;
#pragma unroll
        for (int q = 0; q < 4; q++) {
            float4 xv = *(const float4*)(xr + q * 4);
            float4 wv = *(const float4*)(wr + q * 4);
            sX[(lk + q * 4 + 0) * 132 + lrow] = xv.x;
            sX[(lk + q * 4 + 1) * 132 + lrow] = xv.y;
            sX[(lk + q * 4 + 2) * 132 + lrow] = xv.z;
            sX[(lk + q * 4 + 3) * 132 + lrow] = xv.w;
            sW[(lk + q * 4 + 0) * 132 + lrow] = wv.x;
            sW[(lk + q * 4 + 1) * 132 + lrow] = wv.y;
            sW[(lk + q * 4 + 2) * 132 + lrow] = wv.z;
            sW[(lk + q * 4 + 3) * 132 + lrow] = wv.w;
        }
        __syncthreads();
#pragma unroll
        for (int kk = 0; kk < 32; kk++) {
            float4 a0 = *(const float4*)(sX + kk * 132 + ty * 8);
            float4 a1 = *(const float4*)(sX + kk * 132 + ty * 8 + 4);
            const u64* bW = (const u64*)(sW + kk * 132 + tx * 8);
            u64 bv0 = bW[0], bv1 = bW[1], bv2 = bW[2], bv3 = bW[3];
            float a[8] = {a0.x,a0.y,a0.z,a0.w,a1.x,a1.y,a1.z,a1.w};
#pragma unroll
            for (int i = 0; i < 8; i++) {
                u64 ap = pk2(a[i], a[i]);
                fma2(acc[i][0], ap, bv0);
                fma2(acc[i][1], ap, bv1);
                fma2(acc[i][2], ap, bv2);
                fma2(acc[i][3], ap, bv3);
            }
        }
        __syncthreads();
    }
#pragma unroll
    for (int i = 0; i < 8; i++) {
        int m = m0 + ty * 8 + i;
        if (m >= NPAR) continue;
        float* dst = out + (size_t)m * H + n0 + tx * 8;
#pragma unroll
        for (int j = 0; j < 4; j++) {
            float2 v = upk2(acc[i][j]);
            dst[j * 2 + 0] = v.x + bias[n0 + tx * 8 + j * 2 + 0];
            dst[j * 2 + 1] = v.y + bias[n0 + tx * 8 + j * 2 + 1];
        }
    }
}

// ---------------- launch 4: persistent level-synchronous main ----------------
__device__ __forceinline__ void gridbar(int nb, int& sense) {
    __syncthreads();
    if (threadIdx.x == 0) {
        sense ^= 1;
        __threadfence();
        if (atomicAdd(&g_barcnt, 1) == nb - 1) {
            atomicExch(&g_barcnt, 0);
            __threadfence();
            g_barsense = sense;
        } else {
            while (g_barsense != sense) __nanosleep(32);
        }
        __threadfence();
    }
    __syncthreads();
}

#define AH(buf,k,head) (((buf)*4+(k))*8+(head))*65

__device__ int attn_core(int p, const int* __restrict__ tree, float* SBUF,
                         int* s_child, float* s_sc, float* s_p) {
    int tid = threadIdx.x;
    __syncthreads();
    if (tid < DEG) s_child[tid] = tree[p * DEG + tid];
    __syncthreads();
#pragma unroll
    for (int j = 0; j < 8; j++) {
        int idx = tid + j * 256;
        int k = idx >> 9, col = idx & 511, head = col >> 6, d = col & 63;
        int c = s_child[k];
        SBUF[AH(0, k, head) + d] = (c > -1) ? __ldcg(&g_nodeh[(size_t)c * H + col]) : 0.f;
    }
    __syncthreads();
    int cur = 0;
    for (int layer = 0; layer < NLAYER; layer++) {
        if (tid < 128) {
            int head = tid >> 4, q = (tid >> 2) & 3, kk = tid & 3;
            const float* hq = &SBUF[AH(cur, q, head)];
            const float* hk = &SBUF[AH(cur, kk, head)];
            float s = 0.f;
#pragma unroll
            for (int d = 0; d < DK; d++) s += hq[d] * hk[d];
            s *= 0.125f;
            if (s_child[kk] <= -1) s = -1e9f;
            s_sc[(head * 4 + q) * 4 + kk] = s;
        }
        __syncthreads();
        if (tid < 32) {
            int head = tid >> 2, q = tid & 3;
            const float* r = &s_sc[(head * 4 + q) * 4];
            float m = fmaxf(fmaxf(r[0], r[1]), fmaxf(r[2], r[3]));
            float e0 = __expf(r[0] - m), e1 = __expf(r[1] - m);
            float e2 = __expf(r[2] - m), e3 = __expf(r[3] - m);
            float inv = 1.f / (e0 + e1 + e2 + e3);
            float* pr = &s_p[(head * 4 + q) * 4];
            pr[0] = e0 * inv; pr[1] = e1 * inv; pr[2] = e2 * inv; pr[3] = e3 * inv;
        }
        __syncthreads();
        int nxt = cur ^ 1;
#pragma unroll
        for (int j = 0; j < 2; j++) {
            int col = tid + j * 256, head = col >> 6, d = col & 63;
            float v0 = SBUF[AH(cur, 0, head) + d];
            float v1 = SBUF[AH(cur, 1, head) + d];
            float v2 = SBUF[AH(cur, 2, head) + d];
            float v3 = SBUF[AH(cur, 3, head) + d];
#pragma unroll
            for (int q = 0; q < 4; q++) {
                const float* pr = &s_p[(head * 4 + q) * 4];
                SBUF[AH(nxt, q, head) + d] = pr[0] * v0 + pr[1] * v1 + pr[2] * v2 + pr[3] * v3;
            }
        }
        __syncthreads();
        cur = nxt;
    }
    return cur;
}

__device__ void phaseA(int row, const int* __restrict__ tree, float* SBUF,
                       int* s_child, float* s_sc, float* s_p) {
    int tid = threadIdx.x;
    int p = g_order[row];
    int cur = attn_core(p, tree, SBUF, s_child, s_sc, s_p);
    int cc = (s_child[0] > -1) + (s_child[1] > -1) + (s_child[2] > -1) + (s_child[3] > -1);
    float denom = (float)max(cc, 1);
#pragma unroll
    for (int j = 0; j < 2; j++) {
        int col = tid + j * 256, head = col >> 6, d = col & 63;
        float m = 0.f;
#pragma unroll
        for (int k = 0; k < DEG; k++)
            if (s_child[k] > -1) m += SBUF[AH(cur, k, head) + d];
        __stcg(&g_memv[(size_t)row * H + col], m / denom);
    }
}

// cooperative matvec path for tiny levels
__device__ void coopB(int start, int cnt, const float* __restrict__ Uz,
                      const float* __restrict__ Ur) {
    int gw = blockIdx.x * 8 + (threadIdx.x >> 5);
    int nw = gridDim.x * 8;
    int lane = threadIdx.x & 31;
    int ntask = cnt * H;
    for (int t = gw; t < ntask; t += nw) {
        int i = t >> 9, d = t & 511;
        int row = start + i;
        const float4* mv = (const float4*)&g_memv[(size_t)row * H];
        const float4* uz = (const float4*)(Uz + (size_t)d * H);
        const float4* ur = (const float4*)(Ur + (size_t)d * H);
        float az = 0.f, ar = 0.f;
#pragma unroll
        for (int j = 0; j < 4; j++) {
            float4 m = __ldcg(&mv[lane + j * 32]);
            float4 a = __ldg(&uz[lane + j * 32]);
            az += a.x * m.x + a.y * m.y + a.z * m.z + a.w * m.w;
            float4 b = __ldg(&ur[lane + j * 32]);
            ar += b.x * m.x + b.y * m.y + b.z * m.z + b.w * m.w;
        }
#pragma unroll
        for (int o = 16; o; o >>= 1) {
            az += __shfl_down_sync(0xffffffffu, az, o);
            ar += __shfl_down_sync(0xffffffffu, ar, o);
        }
        if (lane == 0) {
            int p = g_order[row];
            size_t rb = (size_t)row * H + d;
            float z = sigf(__ldcg(&g_gz0[(size_t)p * H + d]) + az);
            float r = sigf(__ldcg(&g_gr0[(size_t)p * H + d]) + ar);
            float mem = __ldcg(&g_memv[rb]);
            __stcg(&g_zv[rb], z);
            __stcg(&g_mrv[rb], mem * r);
        }
    }
}

__device__ void coopC(int start, int cnt, const float* __restrict__ Uh) {
    int gw = blockIdx.x * 8 + (threadIdx.x >> 5);
    int nw = gridDim.x * 8;
    int lane = threadIdx.x & 31;
    int ntask = cnt * H;
    for (int t = gw; t < ntask; t += nw) {
        int i = t >> 9, d = t & 511;
        int row = start + i;
        const float4* mrv = (const float4*)&g_mrv[(size_t)row * H];
        const float4* uh = (const float4*)(Uh + (size_t)d * H);
        float ah = 0.f;
#pragma unroll
        for (int j = 0; j < 4; j++) {
            float4 m = __ldcg(&mrv[lane + j * 32]);
            float4 a = __ldg(&uh[lane + j * 32]);
            ah += a.x * m.x + a.y * m.y + a.z * m.z + a.w * m.w;
        }
#pragma unroll
        for (int o = 16; o; o >>= 1) ah += __shfl_down_sync(0xffffffffu, ah, o);
        if (lane == 0) {
            int p = g_order[row];
            size_t rb = (size_t)row * H + d;
            float c = tanhf(__ldcg(&g_gh0[(size_t)p * H + d]) + ah);
            float z = __ldcg(&g_zv[rb]);
            float mem = __ldcg(&g_memv[rb]);
            __stcg(&g_nodeh[(size_t)(NLEAF + p) * H + d], z * mem + (1.f - z) * c);
        }
    }
}

// GEMM tile phases with f32x2 cores: BM=32, BN in {32,64}; weight stride BN+2 (8B aligned)
template<int BN>
__device__ void phaseB(int start, int cnt, int t,
                       const float* __restrict__ Uz, const float* __restrict__ Ur,
                       float* SBUF, int* s_pid) {
    const int NT = H / BN;
    const int WS = BN + 2;
    int m0 = (t / NT) * 32, n0 = (t % NT) * BN;
    float* sA  = SBUF;
    float* sWz = SBUF + 1056;
    float* sWr = SBUF + 1056 + 32 * WS;
    int tid = threadIdx.x;
    const int TX = BN / 4;         // 16 or 8
    const int RM = BN / 32;        // 2 or 1
    int ty = tid / TX, tx = tid % TX;
    int am = tid >> 3, ak = (tid & 7) * 4;
    u64 az[RM][2], ar[RM][2];
#pragma unroll
    for (int i = 0; i < RM; i++)
#pragma unroll
        for (int j = 0; j < 2; j++) { az[i][j] = 0ULL; ar[i][j] = 0ULL; }
    __syncthreads();
    if (tid < 32) s_pid[tid] = g_order[start + min(m0 + tid, cnt - 1)];
    int rrow = start + ((m0 + am < cnt) ? m0 + am : 0);
    for (int kc = 0; kc < H; kc += 32) {
        float4 a = __ldcg((const float4*)&g_memv[(size_t)rrow * H + kc + ak]);
        sA[(ak + 0) * 33 + am] = a.x; sA[(ak + 1) * 33 + am] = a.y;
        sA[(ak + 2) * 33 + am] = a.z; sA[(ak + 3) * 33 + am] = a.w;
        if (BN == 64) {
            int wn = tid >> 2, wk = (tid & 3) * 8;
            const float* wz = Uz + (size_t)(n0 + wn) * H + kc + wk;
            const float* wr = Ur + (size_t)(n0 + wn) * H + kc + wk;
#pragma unroll
            for (int q = 0; q < 2; q++) {
                float4 zv = *(const float4*)(wz + q * 4);
                float4 rv = *(const float4*)(wr + q * 4);
                sWz[(wk + q * 4 + 0) * WS + wn] = zv.x;
                sWz[(wk + q * 4 + 1) * WS + wn] = zv.y;
                sWz[(wk + q * 4 + 2) * WS + wn] = zv.z;
                sWz[(wk + q * 4 + 3) * WS + wn] = zv.w;
                sWr[(wk + q * 4 + 0) * WS + wn] = rv.x;
                sWr[(wk + q * 4 + 1) * WS + wn] = rv.y;
                sWr[(wk + q * 4 + 2) * WS + wn] = rv.z;
                sWr[(wk + q * 4 + 3) * WS + wn] = rv.w;
            }
        } else {
            int wn = tid >> 3, wk = (tid & 7) * 4;
            float4 zv = *(const float4*)(Uz + (size_t)(n0 + wn) * H + kc + wk);
            float4 rv = *(const float4*)(Ur + (size_t)(n0 + wn) * H + kc + wk);
            sWz[(wk + 0) * WS + wn] = zv.x; sWz[(wk + 1) * WS + wn] = zv.y;
            sWz[(wk + 2) * WS + wn] = zv.z; sWz[(wk + 3) * WS + wn] = zv.w;
            sWr[(wk + 0) * WS + wn] = rv.x; sWr[(wk + 1) * WS + wn] = rv.y;
            sWr[(wk + 2) * WS + wn] = rv.z; sWr[(wk + 3) * WS + wn] = rv.w;
        }
        __syncthreads();
#pragma unroll
        for (int kk = 0; kk < 32; kk++) {
            const u64* bz = (const u64*)(sWz + kk * WS + tx * 4);
            const u64* br = (const u64*)(sWr + kk * WS + tx * 4);
            u64 bz0 = bz[0], bz1 = bz[1];
            u64 br0 = br[0], br1 = br[1];
#pragma unroll
            for (int i = 0; i < RM; i++) {
                float av = sA[kk * 33 + ty * RM + i];
                u64 ap = pk2(av, av);
                fma2(az[i][0], ap, bz0); fma2(az[i][1], ap, bz1);
                fma2(ar[i][0], ap, br0); fma2(ar[i][1], ap, br1);
            }
        }
        __syncthreads();
    }
#pragma unroll
    for (int mi = 0; mi < RM; mi++) {
        int m = m0 + ty * RM + mi;
        if (m >= cnt) continue;
        int p = s_pid[ty * RM + mi];
        size_t rb = (size_t)(start + m) * H + n0 + tx * 4;
        size_t pb = (size_t)p * H + n0 + tx * 4;
        float vz[4] = { upk2(az[mi][0]).x, upk2(az[mi][0]).y,
                        upk2(az[mi][1]).x, upk2(az[mi][1]).y };
        float vr[4] = { upk2(ar[mi][0]).x, upk2(ar[mi][0]).y,
                        upk2(ar[mi][1]).x, upk2(ar[mi][1]).y };
#pragma unroll
        for (int n = 0; n < 4; n++) {
            float z = sigf(__ldcg(&g_gz0[pb + n]) + vz[n]);
            float r = sigf(__ldcg(&g_gr0[pb + n]) + vr[n]);
            float mem = __ldcg(&g_memv[rb + n]);
            __stcg(&g_zv[rb + n], z);
            __stcg(&g_mrv[rb + n], mem * r);
        }
    }
}

template<int BN>
__device__ void phaseC(int start, int cnt, int t,
                       const float* __restrict__ Uh, float* SBUF, int* s_pid) {
    const int NT = H / BN;
    const int WS = BN + 2;
    int m0 = (t / NT) * 32, n0 = (t % NT) * BN;
    float* sA = SBUF;
    float* sW = SBUF + 1056;
    int tid = threadIdx.x;
    const int TX = BN / 4;
    const int RM = BN / 32;
    int ty = tid / TX, tx = tid % TX;
    int am = tid >> 3, ak = (tid & 7) * 4;
    u64 ah[RM][2];
#pragma unroll
    for (int i = 0; i < RM; i++) { ah[i][0] = 0ULL; ah[i][1] = 0ULL; }
    __syncthreads();
    if (tid < 32) s_pid[tid] = g_order[start + min(m0 + tid, cnt - 1)];
    int rrow = start + ((m0 + am < cnt) ? m0 + am : 0);
    for (int kc = 0; kc < H; kc += 32) {
        float4 a = __ldcg((const float4*)&g_mrv[(size_t)rrow * H + kc + ak]);
        sA[(ak + 0) * 33 + am] = a.x; sA[(ak + 1) * 33 + am] = a.y;
        sA[(ak + 2) * 33 + am] = a.z; sA[(ak + 3) * 33 + am] = a.w;
        if (BN == 64) {
            int wn = tid >> 2, wk = (tid & 3) * 8;
            const float* wh = Uh + (size_t)(n0 + wn) * H + kc + wk;
#pragma unroll
            for (int q = 0; q < 2; q++) {
                float4 hv = *(const float4*)(wh + q * 4);
                sW[(wk + q * 4 + 0) * WS + wn] = hv.x;
                sW[(wk + q * 4 + 1) * WS + wn] = hv.y;
                sW[(wk + q * 4 + 2) * WS + wn] = hv.z;
                sW[(wk + q * 4 + 3) * WS + wn] = hv.w;
            }
        } else {
            int wn = tid >> 3, wk = (tid & 7) * 4;
            float4 hv = *(const float4*)(Uh + (size_t)(n0 + wn) * H + kc + wk);
            sW[(wk + 0) * WS + wn] = hv.x; sW[(wk + 1) * WS + wn] = hv.y;
            sW[(wk + 2) * WS + wn] = hv.z; sW[(wk + 3) * WS + wn] = hv.w;
        }
        __syncthreads();
#pragma unroll
        for (int kk = 0; kk < 32; kk++) {
            const u64* bh = (const u64*)(sW + kk * WS + tx * 4);
            u64 b0 = bh[0], b1 = bh[1];
#pragma unroll
            for (int i = 0; i < RM; i++) {
                float av = sA[kk * 33 + ty * RM + i];
                u64 ap = pk2(av, av);
                fma2(ah[i][0], ap, b0);
                fma2(ah[i][1], ap, b1);
            }
        }
        __syncthreads();
    }
#pragma unroll
    for (int mi = 0; mi < RM; mi++) {
        int m = m0 + ty * RM + mi;
        if (m >= cnt) continue;
        int p = s_pid[ty * RM + mi];
        size_t rb = (size_t)(start + m) * H + n0 + tx * 4;
        size_t pb = (size_t)p * H + n0 + tx * 4;
        float vh[4] = { upk2(ah[mi][0]).x, upk2(ah[mi][0]).y,
                        upk2(ah[mi][1]).x, upk2(ah[mi][1]).y };
#pragma unroll
        for (int n = 0; n < 4; n++) {
            float c = tanhf(__ldcg(&g_gh0[pb + n]) + vh[n]);
            float z = __ldcg(&g_zv[rb + n]);
            float mem = __ldcg(&g_memv[rb + n]);
            __stcg(&g_nodeh[(size_t)(NLEAF + p) * H + n0 + tx * 4 + n],
                   z * mem + (1.f - z) * c);
        }
    }
}

__global__ void __launch_bounds__(256) k_main(
    const int* __restrict__ tree,
    const float* __restrict__ Uz, const float* __restrict__ Ur,
    const float* __restrict__ Uh)
{
    __shared__ float SBUF[5696];
    __shared__ float s_sc[128], s_p[128];
    __shared__ int s_child[DEG], s_pid[32];
    int nb = gridDim.x;
    int sense = 0;
    int tid = threadIdx.x;
    int gstride = nb * 256;

    // ---- leveling prologue ----
    for (int p = blockIdx.x * 256 + tid; p < NPAR; p += gstride) {
        int lv = 0;
#pragma unroll
        for (int k = 0; k < DEG; k++) {
            int c = tree[p * DEG + k];
            if (c >= NLEAF) {
                int v;
                while ((v = atomicAdd(&g_lvl[c - NLEAF], 0)) < 0) __nanosleep(40);
                lv = max(lv, v + 1);
            }
        }
        if (lv > LMAX - 1) lv = LMAX - 1;
        atomicExch(&g_lvl[p], lv);
    }
    gridbar(nb, sense);
    for (int p = blockIdx.x * 256 + tid; p < NPAR; p += gstride)
        atomicAdd(&g_hist[g_lvl[p]], 1);
    gridbar(nb, sense);
    if (blockIdx.x == 0 && tid == 0) {
        int acc = 0, nl = 1;
        for (int i = 0; i < LMAX; i++) {
            g_lstart[i] = acc; g_lofs[i] = acc;
            acc += g_hist[i];
            if (g_hist[i] > 0) nl = i + 1;
        }
        g_nlev = nl;
    }
    gridbar(nb, sense);
    for (int p = blockIdx.x * 256 + tid; p < NPAR; p += gstride)
        g_order[atomicAdd(&g_lofs[g_lvl[p]], 1)] = p;
    gridbar(nb, sense);

    int nlev = g_nlev;
    for (int l = 0; l < nlev; l++) {
        int start = g_lstart[l], cnt = g_hist[l];
        if (cnt == 0) continue;
        for (int j = blockIdx.x; j < cnt; j += nb)
            phaseA(start + j, tree, SBUF, s_child, s_sc, s_p);
        gridbar(nb, sense);
        if (cnt < 32) {
            coopB(start, cnt, Uz, Ur);
            gridbar(nb, sense);
            coopC(start, cnt, Uh);
            gridbar(nb, sense);
        } else {
            int mt = (cnt + 31) >> 5;
            if (mt * 8 >= nb) {
                int nt = mt * 8;
                for (int t = blockIdx.x; t < nt; t += nb)
                    phaseB<64>(start, cnt, t, Uz, Ur, SBUF, s_pid);
                gridbar(nb, sense);
                for (int t = blockIdx.x; t < nt; t += nb)
                    phaseC<64>(start, cnt, t, Uh, SBUF, s_pid);
            } else {
                int nt = mt * 16;
                for (int t = blockIdx.x; t < nt; t += nb)
                    phaseB<32>(start, cnt, t, Uz, Ur, SBUF, s_pid);
                gridbar(nb, sense);
                for (int t = blockIdx.x; t < nt; t += nb)
                    phaseC<32>(start, cnt, t, Uh, SBUF, s_pid);
            }
            gridbar(nb, sense);
        }
    }
}

// ---------------- reductions ----------------
__global__ void k_redmax() {
    int tid = threadIdx.x;
    int b = blockIdx.x;
    const float* base = g_nodeh + (size_t)NLEAF * H;
    float m = -3.4e38f;
    for (int p = b * RED_CHUNK; p < (b + 1) * RED_CHUNK; p++)
        m = fmaxf(m, base[(size_t)p * H + tid]);
    g_pmax[b * H + tid] = m;
}

__global__ void k_final(const float* __restrict__ Wo, const float* __restrict__ bo,
                        float* __restrict__ out) {
    __shared__ float s_f[H];
    __shared__ float s_logit[NCLASS];
    int tid = threadIdx.x;   // 512
    float m = g_pmax[tid];
    for (int b = 1; b < NB_RED; b++) m = fmaxf(m, g_pmax[b * H + tid]);
    s_f[tid] = m;
    __syncthreads();
    int w = tid >> 5, lane = tid & 31;
    if (w < NCLASS) {
        float acc = 0.f;
        for (int j = lane; j < H; j += 32) acc += Wo[w * H + j] * s_f[j];
#pragma unroll
        for (int o = 16; o; o >>= 1) acc += __shfl_down_sync(0xffffffffu, acc, o);
        if (lane == 0) s_logit[w] = acc + bo[w];
    }
    __syncthreads();
    if (tid == 0) {
        float mx = s_logit[0];
        for (int i = 1; i < NCLASS; i++) mx = fmaxf(mx, s_logit[i]);
        float e[NCLASS], s = 0.f;
        for (int i = 0; i < NCLASS; i++) { e[i] = __expf(s_logit[i] - mx); s += e[i]; }
        for (int i = 0; i < NCLASS; i++) out[i] = e[i] / s;
    }
}

extern "C" void kernel_launch(void* const* d_in, const int* in_sizes, int n_in,
                              void* d_out, int out_size) {
    const float* x_word  = (const float*)d_in[0];
    const int*   x_index = (const int*)  d_in[1];
    const int*   tree    = (const int*)  d_in[2];
    const float* E_bu    = (const float*)d_in[3];
    const float* W_z = (const float*)d_in[4];
    const float* U_z = (const float*)d_in[5];
    const float* b_z = (const float*)d_in[6];
    const float* W_r = (const float*)d_in[7];
    const float* U_r = (const float*)d_in[8];
    const float* b_r = (const float*)d_in[9];
    const float* W_h = (const float*)d_in[10];
    const float* U_h = (const float*)d_in[11];
    const float* b_h = (const float*)d_in[12];
    const float* W_out = (const float*)d_in[13];
    const float* b_out = (const float*)d_in[14];
    float* out = (float*)d_out;

    static int nb_main = 0;
    if (nb_main == 0) {
        int dev = 0; cudaGetDevice(&dev);
        int nsm = 0; cudaDeviceGetAttribute(&nsm, cudaDevAttrMultiProcessorCount, dev);
        int perSM = 0;
        cudaOccupancyMaxActiveBlocksPerMultiprocessor(&perSM, k_main, 256, 0);
        if (perSM < 1) perSM = 1;
        nb_main = nsm * perSM;
    }

    dim3 tb(32, 8), tg((VOCAB + 31) / 32, H / 32);
    k_setup<<<tg, tb>>>(E_bu);
    k_embed<<<NTOT, 128>>>(x_word, x_index);
    k_pregemm<<<dim3((NPAR + 127) / 128, H / 128, 3), 256>>>(W_z, b_z, W_r, b_r, W_h, b_h);
    k_main<<<nb_main, 256>>>(tree, U_z, U_r, U_h);
    k_redmax<<<NB_RED, H>>>();
    k_final<<<1, H>>>(W_out, b_out, out);
}

// round 9
// speedup vs baseline: 1.2594x; 1.2025x over previous
#include <cuda_runtime.h>
#include <cstdint>

#define H 512
#define DK 64
#define NCLASS 4
#define VOCAB 5000
#define LW 32
#define NLEAF 20000
#define NPAR 20000
#define NTOT 40000
#define DEG 4
#define NLAYER 5
#define LMAX 256
#define NB_RED 125
#define RED_CHUNK 160

__device__ float g_nodeh[(size_t)NTOT * H];
__device__ float g_xepar[(size_t)NPAR * H];
__device__ float g_EbuT[(size_t)VOCAB * H];
__device__ float g_gz0[(size_t)NPAR * H];
__device__ float g_gr0[(size_t)NPAR * H];
__device__ float g_gh0[(size_t)NPAR * H];
__device__ float g_memv[(size_t)NPAR * H];
__device__ float g_mrv[(size_t)NPAR * H];
__device__ float g_zv[(size_t)NPAR * H];
__device__ unsigned g_whi[(size_t)6 * H * H];   // tf32 hi planes: Wz,Wr,Wh,Uz,Ur,Uh
__device__ unsigned g_wlo[(size_t)6 * H * H];   // tf32 lo planes
__device__ int g_lvl[NPAR];
__device__ int g_hist[LMAX], g_lstart[LMAX], g_lofs[LMAX], g_order[NPAR];
__device__ int g_nlev, g_barcnt;
__device__ volatile int g_barsense;
__device__ float g_pmax[NB_RED * H];

__device__ __forceinline__ float sigf(float x) { return 1.f / (1.f + __expf(-x)); }

__device__ __forceinline__ unsigned f2tf(float x) {
    unsigned u; asm("cvt.rna.tf32.f32 %0, %1;" : "=r"(u) : "f"(x)); return u;
}
__device__ __forceinline__ void mma8(float4& d,
    unsigned a0, unsigned a1, unsigned a2, unsigned a3, unsigned b0, unsigned b1) {
    asm("mma.sync.aligned.m16n8k8.row.col.f32.tf32.tf32.f32 "
        "{%0,%1,%2,%3},{%4,%5,%6,%7},{%8,%9},{%0,%1,%2,%3};"
        : "+f"(d.x), "+f"(d.y), "+f"(d.z), "+f"(d.w)
        : "r"(a0), "r"(a1), "r"(a2), "r"(a3), "r"(b0), "r"(b1));
}
__device__ __forceinline__ unsigned fau(float x) { return __float_as_uint(x); }

// ---------------- launch 1: transpose + init ----------------
__global__ void k_setup(const float* __restrict__ E) {
    __shared__ float t[32][33];
    int x = blockIdx.x * 32 + threadIdx.x;
    int y0 = blockIdx.y * 32;
#pragma unroll
    for (int j = 0; j < 32; j += 8) {
        int y = y0 + threadIdx.y + j;
        t[threadIdx.y + j][threadIdx.x] = (x < VOCAB) ? E[(size_t)y * VOCAB + x] : 0.f;
    }
    __syncthreads();
    int xo = blockIdx.y * 32 + threadIdx.x;
    int yo0 = blockIdx.x * 32;
#pragma unroll
    for (int j = 0; j < 32; j += 8) {
        int yo = yo0 + threadIdx.y + j;
        if (yo < VOCAB) g_EbuT[(size_t)yo * H + xo] = t[threadIdx.x][threadIdx.y + j];
    }
    if (blockIdx.x == 0 && blockIdx.y == 0) {
        int tid = threadIdx.y * 32 + threadIdx.x;
        for (int i = tid; i < NPAR; i += 256) g_lvl[i] = -1;
        if (tid < LMAX) g_hist[tid] = 0;
        if (tid == 0) { g_barcnt = 0; g_barsense = 0; }
    }
}

// ---------------- launch 2: split weights into tf32 hi/lo ----------------
__global__ void k_split(const float* __restrict__ Wz, const float* __restrict__ Wr,
                        const float* __restrict__ Wh, const float* __restrict__ Uz,
                        const float* __restrict__ Ur, const float* __restrict__ Uh) {
    size_t idx = (size_t)blockIdx.x * blockDim.x + threadIdx.x;
    size_t total = (size_t)6 * H * H;
    if (idx >= total) return;
    int m = (int)(idx / (H * H));
    size_t off = idx % (H * H);
    const float* src = m == 0 ? Wz : m == 1 ? Wr : m == 2 ? Wh : m == 3 ? Uz : m == 4 ? Ur : Uh;
    float x = src[off];
    unsigned hi = f2tf(x);
    float hif = __uint_as_float(hi);
    g_whi[idx] = hi;
    g_wlo[idx] = f2tf(x - hif);
}

// ---------------- launch 3: embed ----------------
__global__ void k_embed(const float* __restrict__ xw, const int* __restrict__ xi) {
    int n = blockIdx.x;
    int tid = threadIdx.x;   // 128
    __shared__ float s_w[LW];
    __shared__ int   s_i[LW];
    if (tid < LW) { s_w[tid] = xw[n * LW + tid]; s_i[tid] = xi[n * LW + tid]; }
    __syncthreads();
    float4 acc = make_float4(0.f, 0.f, 0.f, 0.f);
#pragma unroll 8
    for (int l = 0; l < LW; l++) {
        float4 e = ((const float4*)(g_EbuT + (size_t)s_i[l] * H))[tid];
        float w = s_w[l];
        acc.x += w * e.x; acc.y += w * e.y; acc.z += w * e.z; acc.w += w * e.w;
    }
    float4* dst = (n < NLEAF) ? (float4*)(g_nodeh + (size_t)n * H)
                              : (float4*)(g_xepar + (size_t)(n - NLEAF) * H);
    dst[tid] = acc;
}

// ---------------- launch 4: pre-GEMM via 3xTF32 mma ----------------
// BM=64, BN=64, BK=32; 256 thr = 8 warps: warp w: mtile=w&3 (16 rows), nhalf=(w>>2)*32
__global__ void __launch_bounds__(256) k_pregemm(
    const float* __restrict__ bz, const float* __restrict__ br, const float* __restrict__ bh)
{
    __shared__ float SM[9216];
    float* sAhi = SM;               // 64*36
    float* sAlo = SM + 2304;
    unsigned* sBh = (unsigned*)SM + 4608;
    unsigned* sBl = (unsigned*)SM + 6912;
    int mat = blockIdx.z;
    const float* bias = mat == 0 ? bz : mat == 1 ? br : bh;
    float* out = mat == 0 ? g_gz0 : mat == 1 ? g_gr0 : g_gh0;
    int m0 = blockIdx.x * 64, n0 = blockIdx.y * 64;
    int tid = threadIdx.x;
    int w = tid >> 5, lane = tid & 31;
    int mt16 = (w & 3) * 16, nh = (w >> 2) * 32;
    float4 c[4];
#pragma unroll
    for (int i = 0; i < 4; i++) c[i] = make_float4(0.f, 0.f, 0.f, 0.f);
    int arow = tid >> 2, ak = (tid & 3) * 8;
    int xm = min(m0 + arow, NPAR - 1);
    const unsigned* gbh = g_whi + (size_t)mat * H * H;
    const unsigned* gbl = g_wlo + (size_t)mat * H * H;
    for (int kc = 0; kc < H; kc += 32) {
        // stage A with split
        const float* xr = g_xepar + (size_t)xm * H + kc + ak;
#pragma unroll
        for (int q = 0; q < 2; q++) {
            float4 v = *(const float4*)(xr + q * 4);
            float vv[4] = {v.x, v.y, v.z, v.w};
#pragma unroll
            for (int j = 0; j < 4; j++) {
                unsigned h = f2tf(vv[j]);
                int o = arow * 36 + ak + q * 4 + j;
                sAhi[o] = __uint_as_float(h);
                sAlo[o] = __uint_as_float(f2tf(vv[j] - __uint_as_float(h)));
            }
        }
        // stage B (presplit)
        const unsigned* ph = gbh + (size_t)(n0 + arow) * H + kc + ak;
        const unsigned* pl = gbl + (size_t)(n0 + arow) * H + kc + ak;
#pragma unroll
        for (int q = 0; q < 2; q++) {
            uint4 hv = *(const uint4*)(ph + q * 4);
            uint4 lv = *(const uint4*)(pl + q * 4);
            int o = arow * 36 + ak + q * 4;
            sBh[o] = hv.x; sBh[o + 1] = hv.y; sBh[o + 2] = hv.z; sBh[o + 3] = hv.w;
            sBl[o] = lv.x; sBl[o + 1] = lv.y; sBl[o + 2] = lv.z; sBl[o + 3] = lv.w;
        }
        __syncthreads();
#pragma unroll
        for (int k8 = 0; k8 < 32; k8 += 8) {
            int ab = (mt16 + (lane >> 2)) * 36 + k8 + (lane & 3);
            unsigned ah0 = fau(sAhi[ab]),       ah1 = fau(sAhi[ab + 288]);
            unsigned ah2 = fau(sAhi[ab + 4]),   ah3 = fau(sAhi[ab + 292]);
            unsigned al0 = fau(sAlo[ab]),       al1 = fau(sAlo[ab + 288]);
            unsigned al2 = fau(sAlo[ab + 4]),   al3 = fau(sAlo[ab + 292]);
#pragma unroll
            for (int nt = 0; nt < 4; nt++) {
                int bb = (nh + nt * 8 + (lane >> 2)) * 36 + k8 + (lane & 3);
                unsigned bh0 = sBh[bb], bh1 = sBh[bb + 4];
                unsigned bl0 = sBl[bb], bl1 = sBl[bb + 4];
                mma8(c[nt], ah0, ah1, ah2, ah3, bh0, bh1);
                mma8(c[nt], ah0, ah1, ah2, ah3, bl0, bl1);
                mma8(c[nt], al0, al1, al2, al3, bh0, bh1);
            }
        }
        __syncthreads();
    }
#pragma unroll
    for (int nt = 0; nt < 4; nt++) {
        float vals[4] = {c[nt].x, c[nt].y, c[nt].z, c[nt].w};
#pragma unroll
        for (int rr = 0; rr < 2; rr++) {
            int m = m0 + mt16 + (lane >> 2) + rr * 8;
            if (m >= NPAR) continue;
#pragma unroll
            for (int cc = 0; cc < 2; cc++) {
                int d = n0 + nh + nt * 8 + 2 * (lane & 3) + cc;
                out[(size_t)m * H + d] = vals[rr * 2 + cc] + bias[d];
            }
        }
    }
}

// ---------------- launch 5: persistent level-synchronous main ----------------
__device__ __forceinline__ void gridbar(int nb, int& sense) {
    __syncthreads();
    if (threadIdx.x == 0) {
        sense ^= 1;
        __threadfence();
        if (atomicAdd(&g_barcnt, 1) == nb - 1) {
            atomicExch(&g_barcnt, 0);
            __threadfence();
            g_barsense = sense;
        } else {
            while (g_barsense != sense) __nanosleep(32);
        }
        __threadfence();
    }
    __syncthreads();
}

#define AH(buf,k,head) (((buf)*4+(k))*8+(head))*65

__device__ int attn_core(int p, const int* __restrict__ tree, float* SBUF,
                         int* s_child, float* s_sc, float* s_p) {
    int tid = threadIdx.x;
    __syncthreads();
    if (tid < DEG) s_child[tid] = tree[p * DEG + tid];
    __syncthreads();
#pragma unroll
    for (int j = 0; j < 8; j++) {
        int idx = tid + j * 256;
        int k = idx >> 9, col = idx & 511, head = col >> 6, d = col & 63;
        int c = s_child[k];
        SBUF[AH(0, k, head) + d] = (c > -1) ? __ldcg(&g_nodeh[(size_t)c * H + col]) : 0.f;
    }
    __syncthreads();
    int cur = 0;
    for (int layer = 0; layer < NLAYER; layer++) {
        if (tid < 128) {
            int head = tid >> 4, q = (tid >> 2) & 3, kk = tid & 3;
            const float* hq = &SBUF[AH(cur, q, head)];
            const float* hk = &SBUF[AH(cur, kk, head)];
            float s = 0.f;
#pragma unroll
            for (int d = 0; d < DK; d++) s += hq[d] * hk[d];
            s *= 0.125f;
            if (s_child[kk] <= -1) s = -1e9f;
            s_sc[(head * 4 + q) * 4 + kk] = s;
        }
        __syncthreads();
        if (tid < 32) {
            int head = tid >> 2, q = tid & 3;
            const float* r = &s_sc[(head * 4 + q) * 4];
            float m = fmaxf(fmaxf(r[0], r[1]), fmaxf(r[2], r[3]));
            float e0 = __expf(r[0] - m), e1 = __expf(r[1] - m);
            float e2 = __expf(r[2] - m), e3 = __expf(r[3] - m);
            float inv = 1.f / (e0 + e1 + e2 + e3);
            float* pr = &s_p[(head * 4 + q) * 4];
            pr[0] = e0 * inv; pr[1] = e1 * inv; pr[2] = e2 * inv; pr[3] = e3 * inv;
        }
        __syncthreads();
        int nxt = cur ^ 1;
#pragma unroll
        for (int j = 0; j < 2; j++) {
            int col = tid + j * 256, head = col >> 6, d = col & 63;
            float v0 = SBUF[AH(cur, 0, head) + d];
            float v1 = SBUF[AH(cur, 1, head) + d];
            float v2 = SBUF[AH(cur, 2, head) + d];
            float v3 = SBUF[AH(cur, 3, head) + d];
#pragma unroll
            for (int q = 0; q < 4; q++) {
                const float* pr = &s_p[(head * 4 + q) * 4];
                SBUF[AH(nxt, q, head) + d] = pr[0] * v0 + pr[1] * v1 + pr[2] * v2 + pr[3] * v3;
            }
        }
        __syncthreads();
        cur = nxt;
    }
    return cur;
}

__device__ void phaseA(int row, const int* __restrict__ tree, float* SBUF,
                       int* s_child, float* s_sc, float* s_p) {
    int tid = threadIdx.x;
    int p = g_order[row];
    int cur = attn_core(p, tree, SBUF, s_child, s_sc, s_p);
    int cc = (s_child[0] > -1) + (s_child[1] > -1) + (s_child[2] > -1) + (s_child[3] > -1);
    float denom = (float)max(cc, 1);
#pragma unroll
    for (int j = 0; j < 2; j++) {
        int col = tid + j * 256, head = col >> 6, d = col & 63;
        float m = 0.f;
#pragma unroll
        for (int k = 0; k < DEG; k++)
            if (s_child[k] > -1) m += SBUF[AH(cur, k, head) + d];
        __stcg(&g_memv[(size_t)row * H + col], m / denom);
    }
}

// cooperative fp32 matvec path for tiny levels
__device__ void coopB(int start, int cnt, const float* __restrict__ Uz,
                      const float* __restrict__ Ur) {
    int gw = blockIdx.x * 8 + (threadIdx.x >> 5);
    int nw = gridDim.x * 8;
    int lane = threadIdx.x & 31;
    int ntask = cnt * H;
    for (int t = gw; t < ntask; t += nw) {
        int i = t >> 9, d = t & 511;
        int row = start + i;
        const float4* mv = (const float4*)&g_memv[(size_t)row * H];
        const float4* uz = (const float4*)(Uz + (size_t)d * H);
        const float4* ur = (const float4*)(Ur + (size_t)d * H);
        float az = 0.f, ar = 0.f;
#pragma unroll
        for (int j = 0; j < 4; j++) {
            float4 m = __ldcg(&mv[lane + j * 32]);
            float4 a = __ldg(&uz[lane + j * 32]);
            az += a.x * m.x + a.y * m.y + a.z * m.z + a.w * m.w;
            float4 b = __ldg(&ur[lane + j * 32]);
            ar += b.x * m.x + b.y * m.y + b.z * m.z + b.w * m.w;
        }
#pragma unroll
        for (int o = 16; o; o >>= 1) {
            az += __shfl_down_sync(0xffffffffu, az, o);
            ar += __shfl_down_sync(0xffffffffu, ar, o);
        }
        if (lane == 0) {
            int p = g_order[row];
            size_t rb = (size_t)row * H + d;
            float z = sigf(__ldcg(&g_gz0[(size_t)p * H + d]) + az);
            float r = sigf(__ldcg(&g_gr0[(size_t)p * H + d]) + ar);
            float mem = __ldcg(&g_memv[rb]);
            __stcg(&g_zv[rb], z);
            __stcg(&g_mrv[rb], mem * r);
        }
    }
}

__device__ void coopC(int start, int cnt, const float* __restrict__ Uh) {
    int gw = blockIdx.x * 8 + (threadIdx.x >> 5);
    int nw = gridDim.x * 8;
    int lane = threadIdx.x & 31;
    int ntask = cnt * H;
    for (int t = gw; t < ntask; t += nw) {
        int i = t >> 9, d = t & 511;
        int row = start + i;
        const float4* mrv = (const float4*)&g_mrv[(size_t)row * H];
        const float4* uh = (const float4*)(Uh + (size_t)d * H);
        float ah = 0.f;
#pragma unroll
        for (int j = 0; j < 4; j++) {
            float4 m = __ldcg(&mrv[lane + j * 32]);
            float4 a = __ldg(&uh[lane + j * 32]);
            ah += a.x * m.x + a.y * m.y + a.z * m.z + a.w * m.w;
        }
#pragma unroll
        for (int o = 16; o; o >>= 1) ah += __shfl_down_sync(0xffffffffu, ah, o);
        if (lane == 0) {
            int p = g_order[row];
            size_t rb = (size_t)row * H + d;
            float c = tanhf(__ldcg(&g_gh0[(size_t)p * H + d]) + ah);
            float z = __ldcg(&g_zv[rb]);
            float mem = __ldcg(&g_memv[rb]);
            __stcg(&g_nodeh[(size_t)(NLEAF + p) * H + d], z * mem + (1.f - z) * c);
        }
    }
}

// phaseB: BM=32 rows, BN=64 dims, Uz(mat3)+Ur(mat4); 3xTF32 mma
__device__ void phaseB(int start, int cnt, int t, float* SBUF, int* s_pid) {
    int tid = threadIdx.x;
    int m0 = (t >> 3) * 32, n0 = (t & 7) * 64;
    float* sAhi = SBUF;                 // 32*36 = 1152
    float* sAlo = SBUF + 1152;
    unsigned* SB = (unsigned*)SBUF;
    unsigned* sBh0 = SB + 2304;         // each plane 64*36 = 2304
    unsigned* sBl0 = SB + 4608;
    unsigned* sBh1 = SB + 6912;
    unsigned* sBl1 = SB + 9216;
    int w = tid >> 5, lane = tid & 31;
    int mat = w >> 2, nb16 = (w & 3) * 16;
    float4 c[2][2];
#pragma unroll
    for (int i = 0; i < 2; i++)
#pragma unroll
        for (int j = 0; j < 2; j++) c[i][j] = make_float4(0.f, 0.f, 0.f, 0.f);
    __syncthreads();
    if (tid < 32) s_pid[tid] = g_order[start + min(m0 + tid, cnt - 1)];
    int arow = tid >> 3, ak = (tid & 7) * 4;
    int bmat = tid >> 7, brow = (tid & 127) >> 1, bk = (tid & 1) * 16;
    const unsigned* gbh = g_whi + (size_t)(3 + bmat) * H * H + (size_t)(n0 + brow) * H + bk;
    const unsigned* gbl = g_wlo + (size_t)(3 + bmat) * H * H + (size_t)(n0 + brow) * H + bk;
    unsigned* dBh = (bmat == 0 ? sBh0 : sBh1) + brow * 36 + bk;
    unsigned* dBl = (bmat == 0 ? sBl0 : sBl1) + brow * 36 + bk;
    int rrow = start + min(m0 + arow, cnt - 1);
    for (int kc = 0; kc < H; kc += 32) {
        float4 a = __ldcg((const float4*)&g_memv[(size_t)rrow * H + kc + ak]);
        float vv[4] = {a.x, a.y, a.z, a.w};
#pragma unroll
        for (int j = 0; j < 4; j++) {
            unsigned h = f2tf(vv[j]);
            sAhi[arow * 36 + ak + j] = __uint_as_float(h);
            sAlo[arow * 36 + ak + j] = __uint_as_float(f2tf(vv[j] - __uint_as_float(h)));
        }
#pragma unroll
        for (int q = 0; q < 4; q++) {
            uint4 hv = __ldg((const uint4*)(gbh + kc + q * 4));
            uint4 lv = __ldg((const uint4*)(gbl + kc + q * 4));
            dBh[q * 4] = hv.x; dBh[q * 4 + 1] = hv.y; dBh[q * 4 + 2] = hv.z; dBh[q * 4 + 3] = hv.w;
            dBl[q * 4] = lv.x; dBl[q * 4 + 1] = lv.y; dBl[q * 4 + 2] = lv.z; dBl[q * 4 + 3] = lv.w;
        }
        __syncthreads();
        unsigned* mBh = mat == 0 ? sBh0 : sBh1;
        unsigned* mBl = mat == 0 ? sBl0 : sBl1;
#pragma unroll
        for (int k8 = 0; k8 < 32; k8 += 8) {
            unsigned ah[2][4], al[2][4];
#pragma unroll
            for (int mt = 0; mt < 2; mt++) {
                int ab = (mt * 16 + (lane >> 2)) * 36 + k8 + (lane & 3);
                ah[mt][0] = fau(sAhi[ab]);     ah[mt][1] = fau(sAhi[ab + 288]);
                ah[mt][2] = fau(sAhi[ab + 4]); ah[mt][3] = fau(sAhi[ab + 292]);
                al[mt][0] = fau(sAlo[ab]);     al[mt][1] = fau(sAlo[ab + 288]);
                al[mt][2] = fau(sAlo[ab + 4]); al[mt][3] = fau(sAlo[ab + 292]);
            }
#pragma unroll
            for (int nt = 0; nt < 2; nt++) {
                int bb = (nb16 + nt * 8 + (lane >> 2)) * 36 + k8 + (lane & 3);
                unsigned bh0 = mBh[bb], bh1 = mBh[bb + 4];
                unsigned bl0 = mBl[bb], bl1 = mBl[bb + 4];
#pragma unroll
                for (int mt = 0; mt < 2; mt++) {
                    mma8(c[mt][nt], ah[mt][0], ah[mt][1], ah[mt][2], ah[mt][3], bh0, bh1);
                    mma8(c[mt][nt], ah[mt][0], ah[mt][1], ah[mt][2], ah[mt][3], bl0, bl1);
                    mma8(c[mt][nt], al[mt][0], al[mt][1], al[mt][2], al[mt][3], bh0, bh1);
                }
            }
        }
        __syncthreads();
    }
#pragma unroll
    for (int mt = 0; mt < 2; mt++)
#pragma unroll
    for (int nt = 0; nt < 2; nt++) {
        float vals[4] = {c[mt][nt].x, c[mt][nt].y, c[mt][nt].z, c[mt][nt].w};
#pragma unroll
        for (int rr = 0; rr < 2; rr++) {
            int rl = mt * 16 + (lane >> 2) + rr * 8;
            if (m0 + rl >= cnt) continue;
            int p = s_pid[rl];
#pragma unroll
            for (int cc2 = 0; cc2 < 2; cc2++) {
                int d = n0 + nb16 + nt * 8 + 2 * (lane & 3) + cc2;
                size_t rb = (size_t)(start + m0 + rl) * H + d;
                size_t pb = (size_t)p * H + d;
                float acc = vals[rr * 2 + cc2];
                if (mat == 0) {
                    __stcg(&g_zv[rb], sigf(__ldcg(&g_gz0[pb]) + acc));
                } else {
                    float r = sigf(__ldcg(&g_gr0[pb]) + acc);
                    __stcg(&g_mrv[rb], __ldcg(&g_memv[rb]) * r);
                }
            }
        }
    }
}

// phaseC: BM=32, BN=128, Uh(mat5)
__device__ void phaseC(int start, int cnt, int t, float* SBUF, int* s_pid) {
    int tid = threadIdx.x;
    int m0 = (t >> 2) * 32, n0 = (t & 3) * 128;
    float* sAhi = SBUF;
    float* sAlo = SBUF + 1152;
    unsigned* SB = (unsigned*)SBUF;
    unsigned* sBh = SB + 2304;          // 128*36 = 4608
    unsigned* sBl = SB + 6912;
    int w = tid >> 5, lane = tid & 31;
    int nb16 = w * 16;
    float4 c[2][2];
#pragma unroll
    for (int i = 0; i < 2; i++)
#pragma unroll
        for (int j = 0; j < 2; j++) c[i][j] = make_float4(0.f, 0.f, 0.f, 0.f);
    __syncthreads();
    if (tid < 32) s_pid[tid] = g_order[start + min(m0 + tid, cnt - 1)];
    int arow = tid >> 3, ak = (tid & 7) * 4;
    int brow = tid >> 1, bk = (tid & 1) * 16;
    const unsigned* gbh = g_whi + (size_t)5 * H * H + (size_t)(n0 + brow) * H + bk;
    const unsigned* gbl = g_wlo + (size_t)5 * H * H + (size_t)(n0 + brow) * H + bk;
    unsigned* dBh = sBh + brow * 36 + bk;
    unsigned* dBl = sBl + brow * 36 + bk;
    int rrow = start + min(m0 + arow, cnt - 1);
    for (int kc = 0; kc < H; kc += 32) {
        float4 a = __ldcg((const float4*)&g_mrv[(size_t)rrow * H + kc + ak]);
        float vv[4] = {a.x, a.y, a.z, a.w};
#pragma unroll
        for (int j = 0; j < 4; j++) {
            unsigned h = f2tf(vv[j]);
            sAhi[arow * 36 + ak + j] = __uint_as_float(h);
            sAlo[arow * 36 + ak + j] = __uint_as_float(f2tf(vv[j] - __uint_as_float(h)));
        }
#pragma unroll
        for (int q = 0; q < 4; q++) {
            uint4 hv = __ldg((const uint4*)(gbh + kc + q * 4));
            uint4 lv = __ldg((const uint4*)(gbl + kc + q * 4));
            dBh[q * 4] = hv.x; dBh[q * 4 + 1] = hv.y; dBh[q * 4 + 2] = hv.z; dBh[q * 4 + 3] = hv.w;
            dBl[q * 4] = lv.x; dBl[q * 4 + 1] = lv.y; dBl[q * 4 + 2] = lv.z; dBl[q * 4 + 3] = lv.w;
        }
        __syncthreads();
#pragma unroll
        for (int k8 = 0; k8 < 32; k8 += 8) {
            unsigned ah[2][4], al[2][4];
#pragma unroll
            for (int mt = 0; mt < 2; mt++) {
                int ab = (mt * 16 + (lane >> 2)) * 36 + k8 + (lane & 3);
                ah[mt][0] = fau(sAhi[ab]);     ah[mt][1] = fau(sAhi[ab + 288]);
                ah[mt][2] = fau(sAhi[ab + 4]); ah[mt][3] = fau(sAhi[ab + 292]);
                al[mt][0] = fau(sAlo[ab]);     al[mt][1] = fau(sAlo[ab + 288]);
                al[mt][2] = fau(sAlo[ab + 4]); al[mt][3] = fau(sAlo[ab + 292]);
            }
#pragma unroll
            for (int nt = 0; nt < 2; nt++) {
                int bb = (nb16 + nt * 8 + (lane >> 2)) * 36 + k8 + (lane & 3);
                unsigned bh0 = sBh[bb], bh1 = sBh[bb + 4];
                unsigned bl0 = sBl[bb], bl1 = sBl[bb + 4];
#pragma unroll
                for (int mt = 0; mt < 2; mt++) {
                    mma8(c[mt][nt], ah[mt][0], ah[mt][1], ah[mt][2], ah[mt][3], bh0, bh1);
                    mma8(c[mt][nt], ah[mt][0], ah[mt][1], ah[mt][2], ah[mt][3], bl0, bl1);
                    mma8(c[mt][nt], al[mt][0], al[mt][1], al[mt][2], al[mt][3], bh0, bh1);
                }
            }
        }
        __syncthreads();
    }
#pragma unroll
    for (int mt = 0; mt < 2; mt++)
#pragma unroll
    for (int nt = 0; nt < 2; nt++) {
        float vals[4] = {c[mt][nt].x, c[mt][nt].y, c[mt][nt].z, c[mt][nt].w};
#pragma unroll
        for (int rr = 0; rr < 2; rr++) {
            int rl = mt * 16 + (lane >> 2) + rr * 8;
            if (m0 + rl >= cnt) continue;
            int p = s_pid[rl];
#pragma unroll
            for (int cc2 = 0; cc2 < 2; cc2++) {
                int d = n0 + nb16 + nt * 8 + 2 * (lane & 3) + cc2;
                size_t rb = (size_t)(start + m0 + rl) * H + d;
                size_t pb = (size_t)p * H + d;
                float cval = tanhf(__ldcg(&g_gh0[pb]) + vals[rr * 2 + cc2]);
                float z = __ldcg(&g_zv[rb]);
                float mem = __ldcg(&g_memv[rb]);
                __stcg(&g_nodeh[(size_t)(NLEAF + p) * H + d], z * mem + (1.f - z) * cval);
            }
        }
    }
}

__global__ void __launch_bounds__(256) k_main(
    const int* __restrict__ tree,
    const float* __restrict__ Uz, const float* __restrict__ Ur,
    const float* __restrict__ Uh)
{
    __shared__ float SBUF[11520];
    __shared__ float s_sc[128], s_p[128];
    __shared__ int s_child[DEG], s_pid[32];
    int nb = gridDim.x;
    int sense = 0;
    int tid = threadIdx.x;
    int gstride = nb * 256;

    // ---- leveling prologue ----
    for (int p = blockIdx.x * 256 + tid; p < NPAR; p += gstride) {
        int lv = 0;
#pragma unroll
        for (int k = 0; k < DEG; k++) {
            int c = tree[p * DEG + k];
            if (c >= NLEAF) {
                int v;
                while ((v = atomicAdd(&g_lvl[c - NLEAF], 0)) < 0) __nanosleep(40);
                lv = max(lv, v + 1);
            }
        }
        if (lv > LMAX - 1) lv = LMAX - 1;
        atomicExch(&g_lvl[p], lv);
    }
    gridbar(nb, sense);
    for (int p = blockIdx.x * 256 + tid; p < NPAR; p += gstride)
        atomicAdd(&g_hist[g_lvl[p]], 1);
    gridbar(nb, sense);
    if (blockIdx.x == 0 && tid == 0) {
        int acc = 0, nl = 1;
        for (int i = 0; i < LMAX; i++) {
            g_lstart[i] = acc; g_lofs[i] = acc;
            acc += g_hist[i];
            if (g_hist[i] > 0) nl = i + 1;
        }
        g_nlev = nl;
    }
    gridbar(nb, sense);
    for (int p = blockIdx.x * 256 + tid; p < NPAR; p += gstride)
        g_order[atomicAdd(&g_lofs[g_lvl[p]], 1)] = p;
    gridbar(nb, sense);

    int nlev = g_nlev;
    for (int l = 0; l < nlev; l++) {
        int start = g_lstart[l], cnt = g_hist[l];
        if (cnt == 0) continue;
        for (int j = blockIdx.x; j < cnt; j += nb)
            phaseA(start + j, tree, SBUF, s_child, s_sc, s_p);
        gridbar(nb, sense);
        if (cnt < 32) {
            coopB(start, cnt, Uz, Ur);
            gridbar(nb, sense);
            coopC(start, cnt, Uh);
            gridbar(nb, sense);
        } else {
            int mt = (cnt + 31) >> 5;
            int ntB = mt * 8;
            for (int t = blockIdx.x; t < ntB; t += nb)
                phaseB(start, cnt, t, SBUF, s_pid);
            gridbar(nb, sense);
            int ntC = mt * 4;
            for (int t = blockIdx.x; t < ntC; t += nb)
                phaseC(start, cnt, t, SBUF, s_pid);
            gridbar(nb, sense);
        }
    }
}

// ---------------- reductions ----------------
__global__ void k_redmax() {
    int tid = threadIdx.x;
    int b = blockIdx.x;
    const float* base = g_nodeh + (size_t)NLEAF * H;
    float m = -3.4e38f;
    for (int p = b * RED_CHUNK; p < (b + 1) * RED_CHUNK; p++)
        m = fmaxf(m, base[(size_t)p * H + tid]);
    g_pmax[b * H + tid] = m;
}

__global__ void k_final(const float* __restrict__ Wo, const float* __restrict__ bo,
                        float* __restrict__ out) {
    __shared__ float s_f[H];
    __shared__ float s_logit[NCLASS];
    int tid = threadIdx.x;   // 512
    float m = g_pmax[tid];
    for (int b = 1; b < NB_RED; b++) m = fmaxf(m, g_pmax[b * H + tid]);
    s_f[tid] = m;
    __syncthreads();
    int w = tid >> 5, lane = tid & 31;
    if (w < NCLASS) {
        float acc = 0.f;
        for (int j = lane; j < H; j += 32) acc += Wo[w * H + j] * s_f[j];
#pragma unroll
        for (int o = 16; o; o >>= 1) acc += __shfl_down_sync(0xffffffffu, acc, o);
        if (lane == 0) s_logit[w] = acc + bo[w];
    }
    __syncthreads();
    if (tid == 0) {
        float mx = s_logit[0];
        for (int i = 1; i < NCLASS; i++) mx = fmaxf(mx, s_logit[i]);
        float e[NCLASS], s = 0.f;
        for (int i = 0; i < NCLASS; i++) { e[i] = __expf(s_logit[i] - mx); s += e[i]; }
        for (int i = 0; i < NCLASS; i++) out[i] = e[i] / s;
    }
}

extern "C" void kernel_launch(void* const* d_in, const int* in_sizes, int n_in,
                              void* d_out, int out_size) {
    const float* x_word  = (const float*)d_in[0];
    const int*   x_index = (const int*)  d_in[1];
    const int*   tree    = (const int*)  d_in[2];
    const float* E_bu    = (const float*)d_in[3];
    const float* W_z = (const float*)d_in[4];
    const float* U_z = (const float*)d_in[5];
    const float* b_z = (const float*)d_in[6];
    const float* W_r = (const float*)d_in[7];
    const float* U_r = (const float*)d_in[8];
    const float* b_r = (const float*)d_in[9];
    const float* W_h = (const float*)d_in[10];
    const float* U_h = (const float*)d_in[11];
    const float* b_h = (const float*)d_in[12];
    const float* W_out = (const float*)d_in[13];
    const float* b_out = (const float*)d_in[14];
    float* out = (float*)d_out;

    static int nb_main = 0;
    if (nb_main == 0) {
        int dev = 0; cudaGetDevice(&dev);
        int nsm = 0; cudaDeviceGetAttribute(&nsm, cudaDevAttrMultiProcessorCount, dev);
        int perSM = 0;
        cudaOccupancyMaxActiveBlocksPerMultiprocessor(&perSM, k_main, 256, 0);
        if (perSM < 1) perSM = 1;
        nb_main = nsm * perSM;
    }

    dim3 tb(32, 8), tg((VOCAB + 31) / 32, H / 32);
    k_setup<<<tg, tb>>>(E_bu);
    k_split<<<(6 * H * H + 255) / 256, 256>>>(W_z, W_r, W_h, U_z, U_r, U_h);
    k_embed<<<NTOT, 128>>>(x_word, x_index);
    k_pregemm<<<dim3((NPAR + 63) / 64, H / 64, 3), 256>>>(b_z, b_r, b_h);
    k_main<<<nb_main, 256>>>(tree, U_z, U_r, U_h);
    k_redmax<<<NB_RED, H>>>();
    k_final<<<1, H>>>(W_out, b_out, out);
}